// round 9
// baseline (speedup 1.0000x reference)
#include <cuda_runtime.h>
#include <cuda_fp16.h>
#include <cstdint>
#include <cstddef>

#define MDIM 8192
#define NDIM 2048
#define KDIM 2048

#define BM 128
#define BN 256
#define NS 32               // 2048/64 halfs per stage
#define STAGE_BYTES 49152   // A 16KB fp16 + B 32KB fp16
#define NSTAGES 4
#define SM_BYTES (NSTAGES * STAGE_BYTES)

#define TAU 0.05f
#define FLAG_CAP (1 << 20)

__device__ __half         g_A2[(size_t)MDIM * KDIM];  // [m][k]: fp16(x)
__device__ unsigned char  g_B8[(size_t)NDIM * KDIM];  // [n][k]: fp16-high-byte code of sign(W)
__device__ int            g_flag_count;
__device__ int2           g_flags[FLAG_CAP];

// ---------------- helpers ----------------
__device__ __forceinline__ uint32_t smem_u32(const void* p) {
    uint32_t a;
    asm("{ .reg .u64 t; cvta.to.shared.u64 t, %1; cvt.u32.u64 %0, t; }" : "=r"(a) : "l"(p));
    return a;
}
__device__ __forceinline__ uint32_t swz(uint32_t off) { return off ^ ((off >> 3) & 0x70); }

__device__ __forceinline__ void ldsm4(uint32_t* r, uint32_t addr) {
    asm volatile("ldmatrix.sync.aligned.m8n8.x4.shared.b16 {%0,%1,%2,%3}, [%4];"
                 : "=r"(r[0]), "=r"(r[1]), "=r"(r[2]), "=r"(r[3]) : "r"(addr));
}

__device__ __forceinline__ void mma16816(float* c, const uint32_t* a, uint32_t b0, uint32_t b1) {
    asm volatile(
        "mma.sync.aligned.m16n8k16.row.col.f32.f16.f16.f32 "
        "{%0,%1,%2,%3}, {%4,%5,%6,%7}, {%8,%9}, {%0,%1,%2,%3};"
        : "+f"(c[0]), "+f"(c[1]), "+f"(c[2]), "+f"(c[3])
        : "r"(a[0]), "r"(a[1]), "r"(a[2]), "r"(a[3]), "r"(b0), "r"(b1));
}

__device__ __forceinline__ void cp16(uint32_t dst, const void* src) {
    asm volatile("cp.async.cg.shared.global [%0], [%1], 16;" :: "r"(dst), "l"(src));
}
#define CP_COMMIT() asm volatile("cp.async.commit_group;" ::: "memory")
#define CP_WAIT2()  asm volatile("cp.async.wait_group 2;" ::: "memory")
#define CP_WAIT0()  asm volatile("cp.async.wait_group 0;" ::: "memory")

// expand 4 sign-codes (u32) -> 2x u32 of fp16 pairs (code byte becomes fp16 high byte)
__device__ __forceinline__ uint32_t prmt_lo(uint32_t v) { return __byte_perm(v, 0, 0x1404); }
__device__ __forceinline__ uint32_t prmt_hi(uint32_t v) { return __byte_perm(v, 0, 0x3424); }

// ---------------- prep A: fp16(x), elementwise ----------------
__global__ void prep_a_kernel(const float* __restrict__ x) {
    const size_t i = (size_t)blockIdx.x * blockDim.x + threadIdx.x;  // over float4s
    float4 v = reinterpret_cast<const float4*>(x)[i];
    __half2 h0 = __floats2half2_rn(v.x, v.y);
    __half2 h1 = __floats2half2_rn(v.z, v.w);
    uint2 pk;
    pk.x = *reinterpret_cast<uint32_t*>(&h0);
    pk.y = *reinterpret_cast<uint32_t*>(&h1);
    reinterpret_cast<uint2*>(g_A2)[i] = pk;
    if (i == 0) g_flag_count = 0;
}

// ---------------- prep B: transpose + sign -> fp16 high-byte code ----------------
__global__ void prep_b_kernel(const float* __restrict__ W) {
    __shared__ float tile[32][33];
    int tx = threadIdx.x, ty = threadIdx.y;
    int k0 = blockIdx.x * 32, n0 = blockIdx.y * 32;
    tile[ty][tx] = W[(size_t)(k0 + ty) * NDIM + (n0 + tx)];
    __syncthreads();
    float w = tile[tx][ty];  // (k = k0+tx, n = n0+ty)
    unsigned char code = (w > 0.0f) ? 0x3Cu : ((w < 0.0f) ? 0xBCu : 0x00u);
    g_B8[(size_t)(n0 + ty) * KDIM + (k0 + tx)] = code;
}

// ---------------- GEMM: 128x256 tile, 512 thr, warp tile 32x64, 4-stage ----------------
__global__ void __launch_bounds__(512, 1) bgemm_kernel(float* __restrict__ out) {
    extern __shared__ char smem[];
    const uint32_t sb = smem_u32(smem);
    const int tid = threadIdx.x;
    const int wid = tid >> 5;
    const int l   = tid & 31;
    const int wm  = wid & 3;   // 4 warps over M (32 rows each)
    const int wn  = wid >> 2;  // 4 warps over N (64 cols each)
    const int m0 = blockIdx.x * BM;
    const int n0 = blockIdx.y * BN;

    const uint4* a_src = reinterpret_cast<const uint4*>(g_A2);  // row stride 256 uint4

    // B LDG mapping: thread -> row = tid>>1 (0..255), kpart = (tid&1)*32 bytes
    const int brow = tid >> 1;
    const int bkp  = (tid & 1) * 32;
    const uint4* bp = reinterpret_cast<const uint4*>(
        g_B8 + (size_t)(n0 + brow) * KDIM + bkp);   // stage s at bp[4s], bp[4s+1]
    const uint32_t b_sts_base = (uint32_t)brow * 128 + (uint32_t)(tid & 1) * 64;

    uint32_t aoff[2], boff[4];
    #pragma unroll
    for (int mf = 0; mf < 2; mf++)
        aoff[mf] = (uint32_t)(wm * 32 + mf * 16 + (l & 15)) * 128 + (uint32_t)((l >> 4) & 1) * 16;
    #pragma unroll
    for (int bg = 0; bg < 4; bg++)
        boff[bg] = (uint32_t)(wn * 64 + bg * 16 + (l & 7) + ((l >> 4) & 1) * 8) * 128
                 + (uint32_t)((l >> 3) & 1) * 16;

    float c[2][8][4];
    #pragma unroll
    for (int i = 0; i < 2; i++)
        #pragma unroll
        for (int j = 0; j < 8; j++)
            #pragma unroll
            for (int e = 0; e < 4; e++) c[i][j][e] = 0.0f;

    // A-only cp.async stage
    auto issue_stage_a = [&](int s, int slot) {
        const uint32_t Ab = sb + (uint32_t)slot * STAGE_BYTES;
        #pragma unroll
        for (int i = 0; i < 2; i++) {
            const int cch = tid + i * 512;
            const int row = cch >> 3, j = cch & 7;
            cp16(Ab + swz((uint32_t)row * 128 + j * 16),
                 a_src + (size_t)(m0 + row) * 256 + s * 8 + j);
        }
        CP_COMMIT();
    };

    // expand + store one B stage from a 2x uint4 register buffer
    auto sts_b = [&](int slot, const uint4* q2) {
        char* Bt = smem + (size_t)slot * STAGE_BYTES + 16384;
        #pragma unroll
        for (int h = 0; h < 2; h++) {
            uint4 q = q2[h];
            uint4 o0, o1;
            o0.x = prmt_lo(q.x); o0.y = prmt_hi(q.x);
            o0.z = prmt_lo(q.y); o0.w = prmt_hi(q.y);
            o1.x = prmt_lo(q.z); o1.y = prmt_hi(q.z);
            o1.z = prmt_lo(q.w); o1.w = prmt_hi(q.w);
            *reinterpret_cast<uint4*>(Bt + swz(b_sts_base + h * 32))      = o0;
            *reinterpret_cast<uint4*>(Bt + swz(b_sts_base + h * 32 + 16)) = o1;
        }
    };

    uint4 br[2][2];

    // ---- prolog ----
    br[0][0] = bp[0]; br[0][1] = bp[1];        // B stage 0
    issue_stage_a(0, 0);
    issue_stage_a(1, 1);
    issue_stage_a(2, 2);
    br[1][0] = bp[4]; br[1][1] = bp[5];        // B stage 1
    sts_b(0, br[0]);

    for (int s = 0; s < NS; s++) {
        CP_WAIT2();
        __syncthreads();
        if (s + 3 < NS) issue_stage_a(s + 3, (s + 3) & 3);
        if (s + 1 < NS) sts_b((s + 1) & 3, br[(s + 1) & 1]);
        if (s + 2 < NS) {
            br[s & 1][0] = bp[4 * (s + 2)];
            br[s & 1][1] = bp[4 * (s + 2) + 1];
        }

        const uint32_t Ab = sb + (uint32_t)(s & 3) * STAGE_BYTES;
        const uint32_t Bb = Ab + 16384;
        #pragma unroll
        for (int ks = 0; ks < 4; ks++) {
            uint32_t af[2][4], bq[4][4];
            #pragma unroll
            for (int mf = 0; mf < 2; mf++)
                ldsm4(af[mf], Ab + swz(aoff[mf] + ks * 32));
            #pragma unroll
            for (int bg = 0; bg < 4; bg++)
                ldsm4(bq[bg], Bb + swz(boff[bg] + ks * 32));
            #pragma unroll
            for (int mf = 0; mf < 2; mf++)
                #pragma unroll
                for (int nf = 0; nf < 8; nf++)
                    mma16816(c[mf][nf], af[mf], bq[nf >> 1][(nf & 1) * 2], bq[nf >> 1][(nf & 1) * 2 + 1]);
        }
    }
    CP_WAIT0();

    // ---- epilogue: sign + near-zero flagging ----
    const int g  = l >> 2;
    const int tg = l & 3;
    #pragma unroll
    for (int mf = 0; mf < 2; mf++) {
        const int r0 = m0 + wm * 32 + mf * 16 + g;
        #pragma unroll
        for (int nf = 0; nf < 8; nf++) {
            const int col = n0 + wn * 64 + nf * 8 + 2 * tg;
            #pragma unroll
            for (int e = 0; e < 4; e++) {
                float v = c[mf][nf][e];
                if (fabsf(v) < TAU) {
                    int idx = atomicAdd(&g_flag_count, 1);
                    if (idx < FLAG_CAP)
                        g_flags[idx] = make_int2(r0 + (e >> 1) * 8, col + (e & 1));
                }
            }
            float2 lo, hi;
            lo.x = (c[mf][nf][0] > 0.0f) ? 1.0f : ((c[mf][nf][0] < 0.0f) ? -1.0f : 0.0f);
            lo.y = (c[mf][nf][1] > 0.0f) ? 1.0f : ((c[mf][nf][1] < 0.0f) ? -1.0f : 0.0f);
            hi.x = (c[mf][nf][2] > 0.0f) ? 1.0f : ((c[mf][nf][2] < 0.0f) ? -1.0f : 0.0f);
            hi.y = (c[mf][nf][3] > 0.0f) ? 1.0f : ((c[mf][nf][3] < 0.0f) ? -1.0f : 0.0f);
            *reinterpret_cast<float2*>(out + (size_t)r0 * NDIM + col) = lo;
            *reinterpret_cast<float2*>(out + (size_t)(r0 + 8) * NDIM + col) = hi;
        }
    }
}

// ---------------- fixup: coalesced exact fp64 recompute of flagged outputs ----------------
__global__ void fixup_kernel(const float* __restrict__ x, float* __restrict__ out) {
    const int gw  = (blockIdx.x * blockDim.x + threadIdx.x) >> 5;
    const int lid = threadIdx.x & 31;
    const int nw  = (gridDim.x * blockDim.x) >> 5;
    int cnt = g_flag_count;
    if (cnt > FLAG_CAP) cnt = FLAG_CAP;
    for (int i = gw; i < cnt; i += nw) {
        const int m = g_flags[i].x;
        const int n = g_flags[i].y;
        const float4* xr = reinterpret_cast<const float4*>(x + (size_t)m * KDIM);
        const uint4*  sr = reinterpret_cast<const uint4*>(g_B8 + (size_t)n * KDIM);
        double acc = 0.0;
        for (int k16 = lid; k16 < KDIM / 16; k16 += 32) {
            uint4 cw = sr[k16];
            #pragma unroll
            for (int w = 0; w < 4; w++) {
                uint32_t v = (w == 0) ? cw.x : (w == 1) ? cw.y : (w == 2) ? cw.z : cw.w;
                float4 xv = xr[k16 * 4 + w];
                #pragma unroll
                for (int b = 0; b < 4; b++) {
                    uint32_t code = (v >> (8 * b)) & 0xFFu;
                    float xe = (b == 0) ? xv.x : (b == 1) ? xv.y : (b == 2) ? xv.z : xv.w;
                    if (code == 0x3Cu) acc += (double)xe;
                    else if (code == 0xBCu) acc -= (double)xe;
                }
            }
        }
        #pragma unroll
        for (int o = 16; o; o >>= 1) acc += __shfl_down_sync(0xFFFFFFFFu, acc, o);
        if (lid == 0)
            out[(size_t)m * NDIM + n] = (acc > 0.0) ? 1.0f : ((acc < 0.0) ? -1.0f : 0.0f);
    }
}

// ---------------- launch ----------------
extern "C" void kernel_launch(void* const* d_in, const int* in_sizes, int n_in,
                              void* d_out, int out_size) {
    const float* x = (const float*)d_in[0];
    const float* W = (const float*)d_in[1];
    float* out = (float*)d_out;

    cudaFuncSetAttribute(bgemm_kernel, cudaFuncAttributeMaxDynamicSharedMemorySize, SM_BYTES);

    prep_a_kernel<<<(MDIM * KDIM / 4) / 256, 256>>>(x);
    prep_b_kernel<<<dim3(KDIM / 32, NDIM / 32), dim3(32, 32)>>>(W);
    bgemm_kernel<<<dim3(MDIM / BM, NDIM / BN), 512, SM_BYTES>>>(out);
    fixup_kernel<<<1024, 256>>>(x, out);
}

// round 13
// speedup vs baseline: 1.5708x; 1.5708x over previous
#include <cuda_runtime.h>
#include <cuda_fp16.h>
#include <cstdint>
#include <cstddef>

#define MDIM 8192
#define NDIM 2048
#define KDIM 2048

#define BM 128
#define BN 128
#define NS 32               // 2048/64 halfs per stage
#define STAGE_BYTES 32768   // A 16KB + B 16KB
#define NSTAGES 3
#define SM_BYTES (NSTAGES * STAGE_BYTES)

#define TAU 0.05f
#define FLAG_CAP (1 << 20)

__device__ __half g_A2[(size_t)MDIM * KDIM];   // [m][k]: fp16(x)
__device__ __half g_B2[(size_t)NDIM * KDIM];   // [n][k]: sign(W) as fp16 (n-major)
__device__ int    g_flag_count;
__device__ int2   g_flags[FLAG_CAP];

// ---------------- helpers ----------------
__device__ __forceinline__ uint32_t smem_u32(const void* p) {
    uint32_t a;
    asm("{ .reg .u64 t; cvta.to.shared.u64 t, %1; cvt.u32.u64 %0, t; }" : "=r"(a) : "l"(p));
    return a;
}
__device__ __forceinline__ uint32_t swz(uint32_t off) { return off ^ ((off >> 3) & 0x70); }

__device__ __forceinline__ void ldsm4(uint32_t* r, uint32_t addr) {
    asm volatile("ldmatrix.sync.aligned.m8n8.x4.shared.b16 {%0,%1,%2,%3}, [%4];"
                 : "=r"(r[0]), "=r"(r[1]), "=r"(r[2]), "=r"(r[3]) : "r"(addr));
}

__device__ __forceinline__ void mma16816(float* c, const uint32_t* a, uint32_t b0, uint32_t b1) {
    asm volatile(
        "mma.sync.aligned.m16n8k16.row.col.f32.f16.f16.f32 "
        "{%0,%1,%2,%3}, {%4,%5,%6,%7}, {%8,%9}, {%0,%1,%2,%3};"
        : "+f"(c[0]), "+f"(c[1]), "+f"(c[2]), "+f"(c[3])
        : "r"(a[0]), "r"(a[1]), "r"(a[2]), "r"(a[3]), "r"(b0), "r"(b1));
}

__device__ __forceinline__ void cp16(uint32_t dst, const void* src) {
    asm volatile("cp.async.cg.shared.global [%0], [%1], 16;" :: "r"(dst), "l"(src));
}
#define CP_COMMIT() asm volatile("cp.async.commit_group;" ::: "memory")
#define CP_WAIT1()  asm volatile("cp.async.wait_group 1;" ::: "memory")
#define CP_WAIT0()  asm volatile("cp.async.wait_group 0;" ::: "memory")

// ---------------- prep A: fp16(x), elementwise ----------------
__global__ void prep_a_kernel(const float* __restrict__ x) {
    const size_t i = (size_t)blockIdx.x * blockDim.x + threadIdx.x;  // over float4s
    float4 v = reinterpret_cast<const float4*>(x)[i];
    __half2 h0 = __floats2half2_rn(v.x, v.y);
    __half2 h1 = __floats2half2_rn(v.z, v.w);
    uint2 pk;
    pk.x = *reinterpret_cast<uint32_t*>(&h0);
    pk.y = *reinterpret_cast<uint32_t*>(&h1);
    reinterpret_cast<uint2*>(g_A2)[i] = pk;
    if (i == 0) g_flag_count = 0;
}

// ---------------- prep B: transpose + sign, 64k x 32n tiles, half2 writes ----------------
__global__ void prep_b_kernel(const float* __restrict__ W) {
    __shared__ float tile[64][33];
    const int tx = threadIdx.x, ty = threadIdx.y;
    const int k0 = blockIdx.x * 64, n0 = blockIdx.y * 32;
    tile[ty][tx]      = W[(size_t)(k0 + ty) * NDIM + (n0 + tx)];
    tile[ty + 32][tx] = W[(size_t)(k0 + ty + 32) * NDIM + (n0 + tx)];
    __syncthreads();
    float w0 = tile[2 * tx][ty];
    float w1 = tile[2 * tx + 1][ty];
    float s0 = (w0 > 0.0f) ? 1.0f : ((w0 < 0.0f) ? -1.0f : 0.0f);
    float s1 = (w1 > 0.0f) ? 1.0f : ((w1 < 0.0f) ? -1.0f : 0.0f);
    reinterpret_cast<__half2*>(g_B2 + (size_t)(n0 + ty) * KDIM + k0)[tx] =
        __floats2half2_rn(s0, s1);
}

// ---------------- GEMM: 128x128 tile, 256 thr (4Mx2N warps, 32x64 tile), 3-stage ----------------
__global__ void __launch_bounds__(256, 2) bgemm_kernel(float* __restrict__ out) {
    extern __shared__ char smem[];
    const uint32_t sb = smem_u32(smem);
    const int tid = threadIdx.x;
    const int wid = tid >> 5;
    const int l   = tid & 31;
    const int wm  = wid & 3;   // 4 warps over M (32 rows each)
    const int wn  = wid >> 2;  // 2 warps over N (64 cols each)
    const int m0 = blockIdx.x * BM;
    const int n0 = blockIdx.y * BN;

    const uint4* a_src = reinterpret_cast<const uint4*>(g_A2);  // row stride 256 uint4
    const uint4* b_src = reinterpret_cast<const uint4*>(g_B2);

    uint32_t aoff[2], boff[4];
    #pragma unroll
    for (int mf = 0; mf < 2; mf++)
        aoff[mf] = (uint32_t)(wm * 32 + mf * 16 + (l & 15)) * 128 + (uint32_t)((l >> 4) & 1) * 16;
    #pragma unroll
    for (int bg = 0; bg < 4; bg++)
        boff[bg] = (uint32_t)(wn * 64 + bg * 16 + (l & 7) + ((l >> 4) & 1) * 8) * 128
                 + (uint32_t)((l >> 3) & 1) * 16;

    float c[2][8][4];
    #pragma unroll
    for (int i = 0; i < 2; i++)
        #pragma unroll
        for (int j = 0; j < 8; j++)
            #pragma unroll
            for (int e = 0; e < 4; e++) c[i][j][e] = 0.0f;

    auto issue_stage = [&](int s, int slot) {
        const uint32_t Ab = sb + (uint32_t)slot * STAGE_BYTES;
        const uint32_t Bb = Ab + 16384;
        #pragma unroll
        for (int i = 0; i < 4; i++) {
            const int cch = tid + i * 256;
            const int row = cch >> 3, j = cch & 7;
            cp16(Ab + swz((uint32_t)row * 128 + j * 16),
                 a_src + (size_t)(m0 + row) * 256 + s * 8 + j);
            cp16(Bb + swz((uint32_t)row * 128 + j * 16),
                 b_src + (size_t)(n0 + row) * 256 + s * 8 + j);
        }
        CP_COMMIT();
    };

    issue_stage(0, 0);
    issue_stage(1, 1);

    int slot = 0;
    for (int s = 0; s < NS; s++) {
        CP_WAIT1();
        __syncthreads();
        if (s + 2 < NS) {
            int ns = slot + 2; if (ns >= 3) ns -= 3;
            issue_stage(s + 2, ns);
        }

        const uint32_t Ab = sb + (uint32_t)slot * STAGE_BYTES;
        const uint32_t Bb = Ab + 16384;
        #pragma unroll
        for (int ks = 0; ks < 4; ks++) {
            uint32_t af[2][4], bq[4][4];
            #pragma unroll
            for (int mf = 0; mf < 2; mf++)
                ldsm4(af[mf], Ab + swz(aoff[mf] + ks * 32));
            #pragma unroll
            for (int bg = 0; bg < 4; bg++)
                ldsm4(bq[bg], Bb + swz(boff[bg] + ks * 32));
            #pragma unroll
            for (int mf = 0; mf < 2; mf++)
                #pragma unroll
                for (int nf = 0; nf < 8; nf++)
                    mma16816(c[mf][nf], af[mf], bq[nf >> 1][(nf & 1) * 2], bq[nf >> 1][(nf & 1) * 2 + 1]);
        }
        if (++slot == 3) slot = 0;
    }
    CP_WAIT0();

    // ---- epilogue: sign + near-zero flagging ----
    const int g  = l >> 2;
    const int tg = l & 3;
    #pragma unroll
    for (int mf = 0; mf < 2; mf++) {
        const int r0 = m0 + wm * 32 + mf * 16 + g;
        #pragma unroll
        for (int nf = 0; nf < 8; nf++) {
            const int col = n0 + wn * 64 + nf * 8 + 2 * tg;
            #pragma unroll
            for (int e = 0; e < 4; e++) {
                float v = c[mf][nf][e];
                if (fabsf(v) < TAU) {
                    int idx = atomicAdd(&g_flag_count, 1);
                    if (idx < FLAG_CAP)
                        g_flags[idx] = make_int2(r0 + (e >> 1) * 8, col + (e & 1));
                }
            }
            float2 lo, hi;
            lo.x = (c[mf][nf][0] > 0.0f) ? 1.0f : ((c[mf][nf][0] < 0.0f) ? -1.0f : 0.0f);
            lo.y = (c[mf][nf][1] > 0.0f) ? 1.0f : ((c[mf][nf][1] < 0.0f) ? -1.0f : 0.0f);
            hi.x = (c[mf][nf][2] > 0.0f) ? 1.0f : ((c[mf][nf][2] < 0.0f) ? -1.0f : 0.0f);
            hi.y = (c[mf][nf][3] > 0.0f) ? 1.0f : ((c[mf][nf][3] < 0.0f) ? -1.0f : 0.0f);
            *reinterpret_cast<float2*>(out + (size_t)r0 * NDIM + col) = lo;
            *reinterpret_cast<float2*>(out + (size_t)(r0 + 8) * NDIM + col) = hi;
        }
    }
}

// ---------------- fixup: coalesced exact fp64 recompute of flagged outputs ----------------
__global__ void fixup_kernel(const float* __restrict__ x, float* __restrict__ out) {
    const int gw  = (blockIdx.x * blockDim.x + threadIdx.x) >> 5;
    const int lid = threadIdx.x & 31;
    const int nw  = (gridDim.x * blockDim.x) >> 5;
    int cnt = g_flag_count;
    if (cnt > FLAG_CAP) cnt = FLAG_CAP;
    for (int i = gw; i < cnt; i += nw) {
        const int m = g_flags[i].x;
        const int n = g_flags[i].y;
        const float4* xr = reinterpret_cast<const float4*>(x + (size_t)m * KDIM);
        const __half2* sr = reinterpret_cast<const __half2*>(g_B2 + (size_t)n * KDIM);
        double acc = 0.0;
        #pragma unroll 4
        for (int k4 = lid; k4 < KDIM / 4; k4 += 32) {
            float4 xv = xr[k4];
            __half2 s0 = sr[k4 * 2];
            __half2 s1 = sr[k4 * 2 + 1];
            float2 f0 = __half22float2(s0);
            float2 f1 = __half22float2(s1);
            acc += (double)(xv.x * f0.x) + (double)(xv.y * f0.y)
                 + (double)(xv.z * f1.x) + (double)(xv.w * f1.y);
        }
        #pragma unroll
        for (int o = 16; o; o >>= 1) acc += __shfl_down_sync(0xFFFFFFFFu, acc, o);
        if (lid == 0)
            out[(size_t)m * NDIM + n] = (acc > 0.0) ? 1.0f : ((acc < 0.0) ? -1.0f : 0.0f);
    }
}

// ---------------- launch ----------------
extern "C" void kernel_launch(void* const* d_in, const int* in_sizes, int n_in,
                              void* d_out, int out_size) {
    const float* x = (const float*)d_in[0];
    const float* W = (const float*)d_in[1];
    float* out = (float*)d_out;

    cudaFuncSetAttribute(bgemm_kernel, cudaFuncAttributeMaxDynamicSharedMemorySize, SM_BYTES);

    prep_a_kernel<<<(MDIM * KDIM / 4) / 256, 256>>>(x);
    prep_b_kernel<<<dim3(KDIM / 64, NDIM / 32), dim3(32, 32)>>>(W);
    bgemm_kernel<<<dim3(MDIM / BM, NDIM / BN), 256, SM_BYTES>>>(out);
    fixup_kernel<<<1024, 256>>>(x, out);
}

// round 14
// speedup vs baseline: 1.6387x; 1.0433x over previous
#include <cuda_runtime.h>
#include <cuda_fp16.h>
#include <cstdint>
#include <cstddef>

#define MDIM 8192
#define NDIM 2048
#define KDIM 2048

#define BM 128
#define BN 128
#define NS 32               // 2048/64 halfs per stage
#define STAGE_BYTES 32768   // A 16KB + B 16KB
#define NSTAGES 3
#define SM_BYTES (NSTAGES * STAGE_BYTES)

#define TAU 0.05f
#define FLIST_CAP 2048      // per-CTA flag list capacity (expected ~15)

#define PREP_A_BLOCKS 16384 // (8192*2048/4)/256
#define PREP_B_BLOCKS 2048  // (2048/64)*(2048/32)

__device__ __half g_A2[(size_t)MDIM * KDIM];   // [m][k]: fp16(x)
__device__ __half g_B2[(size_t)NDIM * KDIM];   // [n][k]: sign(W) as fp16 (n-major)

// ---------------- helpers ----------------
__device__ __forceinline__ uint32_t smem_u32(const void* p) {
    uint32_t a;
    asm("{ .reg .u64 t; cvta.to.shared.u64 t, %1; cvt.u32.u64 %0, t; }" : "=r"(a) : "l"(p));
    return a;
}
__device__ __forceinline__ uint32_t swz(uint32_t off) { return off ^ ((off >> 3) & 0x70); }

__device__ __forceinline__ void ldsm4(uint32_t* r, uint32_t addr) {
    asm volatile("ldmatrix.sync.aligned.m8n8.x4.shared.b16 {%0,%1,%2,%3}, [%4];"
                 : "=r"(r[0]), "=r"(r[1]), "=r"(r[2]), "=r"(r[3]) : "r"(addr));
}

__device__ __forceinline__ void mma16816(float* c, const uint32_t* a, uint32_t b0, uint32_t b1) {
    asm volatile(
        "mma.sync.aligned.m16n8k16.row.col.f32.f16.f16.f32 "
        "{%0,%1,%2,%3}, {%4,%5,%6,%7}, {%8,%9}, {%0,%1,%2,%3};"
        : "+f"(c[0]), "+f"(c[1]), "+f"(c[2]), "+f"(c[3])
        : "r"(a[0]), "r"(a[1]), "r"(a[2]), "r"(a[3]), "r"(b0), "r"(b1));
}

__device__ __forceinline__ void cp16(uint32_t dst, const void* src) {
    asm volatile("cp.async.cg.shared.global [%0], [%1], 16;" :: "r"(dst), "l"(src));
}
#define CP_COMMIT() asm volatile("cp.async.commit_group;" ::: "memory")
#define CP_WAIT1()  asm volatile("cp.async.wait_group 1;" ::: "memory")
#define CP_WAIT0()  asm volatile("cp.async.wait_group 0;" ::: "memory")

// ---------------- fused prep: A -> fp16, B -> transposed signs ----------------
__global__ void __launch_bounds__(256) prep_kernel(const float* __restrict__ x,
                                                   const float* __restrict__ W) {
    __shared__ float tile[64][33];
    const int b = blockIdx.x;
    const int t = threadIdx.x;

    if (b < PREP_A_BLOCKS) {
        const size_t i = (size_t)b * 256 + t;  // over float4s of x
        float4 v = reinterpret_cast<const float4*>(x)[i];
        __half2 h0 = __floats2half2_rn(v.x, v.y);
        __half2 h1 = __floats2half2_rn(v.z, v.w);
        uint2 pk;
        pk.x = *reinterpret_cast<uint32_t*>(&h0);
        pk.y = *reinterpret_cast<uint32_t*>(&h1);
        reinterpret_cast<uint2*>(g_A2)[i] = pk;
    } else {
        const int bi = b - PREP_A_BLOCKS;
        const int k0 = (bi & 31) * 64;   // 32 k-tiles
        const int n0 = (bi >> 5) * 32;   // 64 n-tiles
        #pragma unroll
        for (int j = 0; j < 8; j++) {
            const int idx = t + j * 256;
            const int row = idx >> 5, col = idx & 31;
            tile[row][col] = W[(size_t)(k0 + row) * NDIM + (n0 + col)];
        }
        __syncthreads();
        #pragma unroll
        for (int j = 0; j < 4; j++) {
            const int idx = t + j * 256;
            const int nr = idx >> 5, kc = idx & 31;
            float w0 = tile[2 * kc][nr];
            float w1 = tile[2 * kc + 1][nr];
            float s0 = (w0 > 0.0f) ? 1.0f : ((w0 < 0.0f) ? -1.0f : 0.0f);
            float s1 = (w1 > 0.0f) ? 1.0f : ((w1 < 0.0f) ? -1.0f : 0.0f);
            reinterpret_cast<__half2*>(g_B2 + (size_t)(n0 + nr) * KDIM + k0)[kc] =
                __floats2half2_rn(s0, s1);
        }
    }
}

// ---------------- GEMM: 128x128 tile, 256 thr, 3-stage, fused exact self-fixup ----------------
__global__ void __launch_bounds__(256, 2) bgemm_kernel(const float* __restrict__ x,
                                                       float* __restrict__ out) {
    extern __shared__ char smem[];
    const uint32_t sb = smem_u32(smem);
    const int tid = threadIdx.x;
    const int wid = tid >> 5;
    const int l   = tid & 31;
    const int wm  = wid & 3;   // 4 warps over M (32 rows each)
    const int wn  = wid >> 2;  // 2 warps over N (64 cols each)
    const int m0 = blockIdx.x * BM;
    const int n0 = blockIdx.y * BN;

    const uint4* a_src = reinterpret_cast<const uint4*>(g_A2);  // row stride 256 uint4
    const uint4* b_src = reinterpret_cast<const uint4*>(g_B2);

    uint32_t aoff[2], boff[4];
    #pragma unroll
    for (int mf = 0; mf < 2; mf++)
        aoff[mf] = (uint32_t)(wm * 32 + mf * 16 + (l & 15)) * 128 + (uint32_t)((l >> 4) & 1) * 16;
    #pragma unroll
    for (int bg = 0; bg < 4; bg++)
        boff[bg] = (uint32_t)(wn * 64 + bg * 16 + (l & 7) + ((l >> 4) & 1) * 8) * 128
                 + (uint32_t)((l >> 3) & 1) * 16;

    float c[2][8][4];
    #pragma unroll
    for (int i = 0; i < 2; i++)
        #pragma unroll
        for (int j = 0; j < 8; j++)
            #pragma unroll
            for (int e = 0; e < 4; e++) c[i][j][e] = 0.0f;

    auto issue_stage = [&](int s, int slot) {
        const uint32_t Ab = sb + (uint32_t)slot * STAGE_BYTES;
        const uint32_t Bb = Ab + 16384;
        #pragma unroll
        for (int i = 0; i < 4; i++) {
            const int cch = tid + i * 256;
            const int row = cch >> 3, j = cch & 7;
            cp16(Ab + swz((uint32_t)row * 128 + j * 16),
                 a_src + (size_t)(m0 + row) * 256 + s * 8 + j);
            cp16(Bb + swz((uint32_t)row * 128 + j * 16),
                 b_src + (size_t)(n0 + row) * 256 + s * 8 + j);
        }
        CP_COMMIT();
    };

    issue_stage(0, 0);
    issue_stage(1, 1);

    int slot = 0;
    for (int s = 0; s < NS; s++) {
        CP_WAIT1();
        __syncthreads();
        if (s + 2 < NS) {
            int ns = slot + 2; if (ns >= 3) ns -= 3;
            issue_stage(s + 2, ns);
        }

        const uint32_t Ab = sb + (uint32_t)slot * STAGE_BYTES;
        const uint32_t Bb = Ab + 16384;
        #pragma unroll
        for (int ks = 0; ks < 4; ks++) {
            uint32_t af[2][4], bq[4][4];
            #pragma unroll
            for (int mf = 0; mf < 2; mf++)
                ldsm4(af[mf], Ab + swz(aoff[mf] + ks * 32));
            #pragma unroll
            for (int bg = 0; bg < 4; bg++)
                ldsm4(bq[bg], Bb + swz(boff[bg] + ks * 32));
            #pragma unroll
            for (int mf = 0; mf < 2; mf++)
                #pragma unroll
                for (int nf = 0; nf < 8; nf++)
                    mma16816(c[mf][nf], af[mf], bq[nf >> 1][(nf & 1) * 2], bq[nf >> 1][(nf & 1) * 2 + 1]);
        }
        if (++slot == 3) slot = 0;
    }
    CP_WAIT0();
    __syncthreads();   // all ldsm reads done -> stage smem reusable for flag list

    // ---- flag list in (dead) stage smem ----
    int*  fcnt  = reinterpret_cast<int*>(smem);
    int2* flist = reinterpret_cast<int2*>(smem + 16);
    if (tid == 0) *fcnt = 0;
    __syncthreads();

    // ---- epilogue: sign + near-zero flagging ----
    const int g  = l >> 2;
    const int tg = l & 3;
    #pragma unroll
    for (int mf = 0; mf < 2; mf++) {
        const int r0 = m0 + wm * 32 + mf * 16 + g;
        #pragma unroll
        for (int nf = 0; nf < 8; nf++) {
            const int col = n0 + wn * 64 + nf * 8 + 2 * tg;
            #pragma unroll
            for (int e = 0; e < 4; e++) {
                float v = c[mf][nf][e];
                if (fabsf(v) < TAU) {
                    int idx = atomicAdd(fcnt, 1);
                    if (idx < FLIST_CAP)
                        flist[idx] = make_int2(r0 + (e >> 1) * 8, col + (e & 1));
                }
            }
            float2 lo, hi;
            lo.x = (c[mf][nf][0] > 0.0f) ? 1.0f : ((c[mf][nf][0] < 0.0f) ? -1.0f : 0.0f);
            lo.y = (c[mf][nf][1] > 0.0f) ? 1.0f : ((c[mf][nf][1] < 0.0f) ? -1.0f : 0.0f);
            hi.x = (c[mf][nf][2] > 0.0f) ? 1.0f : ((c[mf][nf][2] < 0.0f) ? -1.0f : 0.0f);
            hi.y = (c[mf][nf][3] > 0.0f) ? 1.0f : ((c[mf][nf][3] < 0.0f) ? -1.0f : 0.0f);
            *reinterpret_cast<float2*>(out + (size_t)r0 * NDIM + col) = lo;
            *reinterpret_cast<float2*>(out + (size_t)(r0 + 8) * NDIM + col) = hi;
        }
    }
    __syncthreads();

    // ---- exact fp64 recompute of this CTA's flagged outputs (warp per flag) ----
    int cnt = *fcnt;
    if (cnt > FLIST_CAP) cnt = FLIST_CAP;
    for (int i = wid; i < cnt; i += 8) {
        const int m = flist[i].x;
        const int n = flist[i].y;
        const float4* xr = reinterpret_cast<const float4*>(x + (size_t)m * KDIM);
        const __half2* sr = reinterpret_cast<const __half2*>(g_B2 + (size_t)n * KDIM);
        double acc = 0.0;
        #pragma unroll 4
        for (int k4 = l; k4 < KDIM / 4; k4 += 32) {
            float4 xv = xr[k4];
            __half2 s0 = sr[k4 * 2];
            __half2 s1 = sr[k4 * 2 + 1];
            float2 f0 = __half22float2(s0);
            float2 f1 = __half22float2(s1);
            acc += (double)(xv.x * f0.x) + (double)(xv.y * f0.y)
                 + (double)(xv.z * f1.x) + (double)(xv.w * f1.y);
        }
        #pragma unroll
        for (int o = 16; o; o >>= 1) acc += __shfl_down_sync(0xFFFFFFFFu, acc, o);
        if (l == 0)
            out[(size_t)m * NDIM + n] = (acc > 0.0) ? 1.0f : ((acc < 0.0) ? -1.0f : 0.0f);
    }
}

// ---------------- launch ----------------
extern "C" void kernel_launch(void* const* d_in, const int* in_sizes, int n_in,
                              void* d_out, int out_size) {
    const float* x = (const float*)d_in[0];
    const float* W = (const float*)d_in[1];
    float* out = (float*)d_out;

    cudaFuncSetAttribute(bgemm_kernel, cudaFuncAttributeMaxDynamicSharedMemorySize, SM_BYTES);

    prep_kernel<<<PREP_A_BLOCKS + PREP_B_BLOCKS, 256>>>(x, W);
    bgemm_kernel<<<dim3(MDIM / BM, NDIM / BN), 256, SM_BYTES>>>(x, out);
}